// round 7
// baseline (speedup 1.0000x reference)
#include <cuda_runtime.h>
#include <cuda_bf16.h>

#define NN 100000
#define NE 800000
#define HID 96
#define IND 64
#define N_TILES (NN / 32)          // 3125
#define BN_EPS 1e-5f
#define GRID_P 304                 // 2 CTAs x 152 SMs (GB300)

// ---------------- persistent device scratch ----------------
// g_h2 holds the PRE-BN activations of the current layer (or embed output with
// identity scale/shift). Consumers apply h = relu(h2*scale + shift) on load.
__device__ float g_h2[NN * HID];
__device__ float g_agg[NN * HID];    // mean-aggregated (post-BN) neighbors
__device__ int   g_deg[NN];
__device__ int   g_off[NN + 1];
__device__ int   g_cur[NN];
__device__ int   g_csr[NE];          // src indices sorted by dst
__device__ float g_sum[HID];
__device__ float g_sq[HID];
__device__ float g_scale[HID];
__device__ float g_shift[HID];

// ---------------- CSR build + state init ----------------
__global__ void zero_deg_kernel() {
    int i = blockIdx.x * blockDim.x + threadIdx.x;
    if (i < NN) { g_deg[i] = 0; g_cur[i] = 0; }
    if (i < HID) {
        g_sum[i] = 0.f; g_sq[i] = 0.f;
        g_scale[i] = 1.f; g_shift[i] = 0.f;   // identity BN for layer-0 input
    }
}

__global__ void count_kernel(const int* __restrict__ dst) {
    int e = blockIdx.x * blockDim.x + threadIdx.x;
    if (e < NE) atomicAdd(&g_deg[dst[e]], 1);
}

__global__ void scan_kernel() {
    __shared__ int ssum[1024];
    int t = threadIdx.x;
    const int CH = (NN + 1023) / 1024;   // 98
    int start = t * CH;
    int end = start + CH; if (end > NN) end = NN;
    int local = 0;
    if (start < NN)
        for (int i = start; i < end; i++) local += g_deg[i];
    ssum[t] = local;
    __syncthreads();
    for (int o = 1; o < 1024; o <<= 1) {
        int v = 0;
        if (t >= o) v = ssum[t - o];
        __syncthreads();
        if (t >= o) ssum[t] += v;
        __syncthreads();
    }
    int run = ssum[t] - local;           // exclusive prefix
    if (start < NN)
        for (int i = start; i < end; i++) { g_off[i] = run; run += g_deg[i]; }
    if (t == 1023) g_off[NN] = ssum[1023];
}

__global__ void place_kernel(const int* __restrict__ src, const int* __restrict__ dst) {
    int e = blockIdx.x * blockDim.x + threadIdx.x;
    if (e < NE) {
        int d = dst[e];
        int p = g_off[d] + atomicAdd(&g_cur[d], 1);
        g_csr[p] = src[e];
    }
}

// ---------------- embedding: h2 = relu(x @ W_emb + b_emb)  (identity BN follows) ----------------
__global__ void __launch_bounds__(128) embed_kernel(const float* __restrict__ x,
                                                    const float* __restrict__ W,
                                                    const float* __restrict__ b) {
    __shared__ float sW[IND * HID];    // 6144 floats
    __shared__ float sX[32 * 65];
    int tx = threadIdx.x;
    for (int i = tx; i < IND * HID; i += 128) sW[i] = W[i];
    int rg = tx >> 4, cg = tx & 15;
    int r = rg * 4, c = cg * 6;
    for (int tile = blockIdx.x; tile < N_TILES; tile += gridDim.x) {
        __syncthreads();
        int rb = tile * 32 * IND;
        for (int i = tx; i < 32 * IND; i += 128)
            sX[(i >> 6) * 65 + (i & 63)] = x[rb + i];
        __syncthreads();
        float acc[4][6];
        #pragma unroll
        for (int i = 0; i < 4; i++)
            #pragma unroll
            for (int j = 0; j < 6; j++) acc[i][j] = 0.f;
        #pragma unroll 8
        for (int k = 0; k < IND; k++) {
            float av[4], wv[6];
            #pragma unroll
            for (int i = 0; i < 4; i++) av[i] = sX[(r + i) * 65 + k];
            #pragma unroll
            for (int j = 0; j < 6; j++) wv[j] = sW[k * HID + c + j];
            #pragma unroll
            for (int i = 0; i < 4; i++)
                #pragma unroll
                for (int j = 0; j < 6; j++)
                    acc[i][j] = fmaf(av[i], wv[j], acc[i][j]);
        }
        int ob = tile * 32 * HID;
        #pragma unroll
        for (int i = 0; i < 4; i++)
            #pragma unroll
            for (int j = 0; j < 6; j++) {
                float v = acc[i][j] + b[c + j];
                g_h2[ob + (r + i) * HID + c + j] = fmaxf(v, 0.f);
            }
    }
}

// ---------------- aggregation: warp per node; applies BN+ReLU on gather ----------------
__global__ void agg_kernel() {
    int w = (blockIdx.x * blockDim.x + threadIdx.x) >> 5;
    int lane = threadIdx.x & 31;
    if (w >= NN) return;
    // per-feature BN params for this lane's 3 features
    float sc0 = g_scale[lane],      sh0 = g_shift[lane];
    float sc1 = g_scale[lane + 32], sh1 = g_shift[lane + 32];
    float sc2 = g_scale[lane + 64], sh2 = g_shift[lane + 64];
    int base = g_off[w];
    int cnt = g_deg[w];
    float a0 = 0.f, a1 = 0.f, a2 = 0.f;
    #pragma unroll 4
    for (int e = 0; e < cnt; e++) {
        int s = g_csr[base + e] * HID;
        a0 += fmaxf(fmaf(g_h2[s + lane],      sc0, sh0), 0.f);
        a1 += fmaxf(fmaf(g_h2[s + lane + 32], sc1, sh1), 0.f);
        a2 += fmaxf(fmaf(g_h2[s + lane + 64], sc2, sh2), 0.f);
    }
    float inv = 1.f / (float)(cnt > 0 ? cnt : 1);
    int o = w * HID;
    g_agg[o + lane]      = a0 * inv;
    g_agg[o + lane + 32] = a1 * inv;
    g_agg[o + lane + 64] = a2 * inv;
}

// ---------------- fused SAGE GEMM: h2' = agg@Wl + bl + BN(h2)@Wr, + BN stats ----------------
// smem: sWl[9216] sWr[9216] sA[32*98] sH[32*98] sScale[96] sShift[96]
#define SA_STRIDE 98
#define GEMM_SMEM_FLOATS (9216 * 2 + 32 * SA_STRIDE * 2 + 2 * HID)
__global__ void __launch_bounds__(128) sage_gemm_kernel(const float* __restrict__ Wl,
                                                        const float* __restrict__ bl,
                                                        const float* __restrict__ Wr) {
    extern __shared__ float sm[];
    float* sWl = sm;
    float* sWr = sm + 9216;
    float* sA  = sm + 18432;
    float* sH  = sm + 18432 + 32 * SA_STRIDE;
    float* sScale = sm + 18432 + 64 * SA_STRIDE;
    float* sShift = sScale + HID;
    int tx = threadIdx.x;
    for (int i = tx; i < HID * HID; i += 128) { sWl[i] = Wl[i]; sWr[i] = Wr[i]; }
    if (tx < HID) { sScale[tx] = g_scale[tx]; sShift[tx] = g_shift[tx]; }
    int rg = tx >> 4, cg = tx & 15;
    int r = rg * 4, c = cg * 6;
    float bv[6];
    #pragma unroll
    for (int j = 0; j < 6; j++) bv[j] = bl[c + j];
    float csum[6], csq[6];
    #pragma unroll
    for (int j = 0; j < 6; j++) { csum[j] = 0.f; csq[j] = 0.f; }

    for (int tile = blockIdx.x; tile < N_TILES; tile += gridDim.x) {
        __syncthreads();
        int rb = tile * 32 * HID;
        for (int i = tx; i < 32 * HID; i += 128) {
            int row = i / HID, k = i - row * HID;
            sA[row * SA_STRIDE + k] = g_agg[rb + i];
            // apply previous layer's BN + ReLU to the root features on load
            sH[row * SA_STRIDE + k] =
                fmaxf(fmaf(g_h2[rb + i], sScale[k], sShift[k]), 0.f);
        }
        __syncthreads();
        float acc[4][6];
        #pragma unroll
        for (int i = 0; i < 4; i++)
            #pragma unroll
            for (int j = 0; j < 6; j++) acc[i][j] = 0.f;
        // k unrolled by 2; all shared loads are 8-byte LDS.64
        #pragma unroll 4
        for (int k = 0; k < HID; k += 2) {
            float2 wl0[3], wr0[3], wl1[3], wr1[3];
            #pragma unroll
            for (int j = 0; j < 3; j++) {
                wl0[j] = *(const float2*)&sWl[k * HID + c + 2 * j];
                wr0[j] = *(const float2*)&sWr[k * HID + c + 2 * j];
                wl1[j] = *(const float2*)&sWl[(k + 1) * HID + c + 2 * j];
                wr1[j] = *(const float2*)&sWr[(k + 1) * HID + c + 2 * j];
            }
            float2 av[4], hv[4];
            #pragma unroll
            for (int i = 0; i < 4; i++) {
                av[i] = *(const float2*)&sA[(r + i) * SA_STRIDE + k];
                hv[i] = *(const float2*)&sH[(r + i) * SA_STRIDE + k];
            }
            #pragma unroll
            for (int i = 0; i < 4; i++) {
                #pragma unroll
                for (int j = 0; j < 3; j++) {
                    acc[i][2*j]   = fmaf(av[i].x, wl0[j].x, acc[i][2*j]);
                    acc[i][2*j+1] = fmaf(av[i].x, wl0[j].y, acc[i][2*j+1]);
                    acc[i][2*j]   = fmaf(hv[i].x, wr0[j].x, acc[i][2*j]);
                    acc[i][2*j+1] = fmaf(hv[i].x, wr0[j].y, acc[i][2*j+1]);
                    acc[i][2*j]   = fmaf(av[i].y, wl1[j].x, acc[i][2*j]);
                    acc[i][2*j+1] = fmaf(av[i].y, wl1[j].y, acc[i][2*j+1]);
                    acc[i][2*j]   = fmaf(hv[i].y, wr1[j].x, acc[i][2*j]);
                    acc[i][2*j+1] = fmaf(hv[i].y, wr1[j].y, acc[i][2*j+1]);
                }
            }
        }
        #pragma unroll
        for (int i = 0; i < 4; i++)
            #pragma unroll
            for (int j = 0; j < 6; j++) {
                float v = acc[i][j] + bv[j];
                g_h2[rb + (r + i) * HID + c + j] = v;   // overwrite: staged copy already in smem
                csum[j] += v;
                csq[j]  = fmaf(v, v, csq[j]);
            }
    }
    // block-level BN stat reduction (reuse sA/sH)
    __syncthreads();
    if (tx < HID) { sA[tx] = 0.f; sH[tx] = 0.f; }
    __syncthreads();
    #pragma unroll
    for (int j = 0; j < 6; j++) {
        atomicAdd(&sA[c + j], csum[j]);
        atomicAdd(&sH[c + j], csq[j]);
    }
    __syncthreads();
    if (tx < HID) {
        atomicAdd(&g_sum[tx], sA[tx]);
        atomicAdd(&g_sq[tx],  sH[tx]);
    }
}

// ---------------- BN finalize (+ reset accumulators for next layer) ----------------
__global__ void bn_finalize_kernel(const float* __restrict__ gamma,
                                   const float* __restrict__ beta) {
    int c = threadIdx.x;
    if (c < HID) {
        const float invN = 1.f / (float)NN;
        float mean = g_sum[c] * invN;
        float var = g_sq[c] * invN - mean * mean;
        var = fmaxf(var, 0.f);
        float sc = gamma[c] * rsqrtf(var + BN_EPS);
        g_scale[c] = sc;
        g_shift[c] = beta[c] - mean * sc;
        g_sum[c] = 0.f;          // reset for next layer (single block, no race)
        g_sq[c]  = 0.f;
    }
}

// ---------------- final MLP on central nodes (applies layer-2 BN inline) ----------------
__global__ void final_kernel(const int* __restrict__ central,
                             const float* __restrict__ W1,
                             const float* __restrict__ b1,
                             const float* __restrict__ W2,
                             const float* __restrict__ b2,
                             float* __restrict__ out) {
    __shared__ float row[HID];
    __shared__ float red[HID];
    int g = blockIdx.x;
    int tx = threadIdx.x;
    int cidx = central[g];
    float raw = g_h2[cidx * HID + tx];
    row[tx] = fmaxf(fmaf(raw, g_scale[tx], g_shift[tx]), 0.f);
    __syncthreads();
    float acc = b1[tx];
    #pragma unroll 8
    for (int k = 0; k < HID; k++)
        acc = fmaf(row[k], W1[k * HID + tx], acc);
    acc = fmaxf(acc, 0.f) * W2[tx];
    red[tx] = acc;
    __syncthreads();
    if (tx < 32) {
        float s = red[tx] + red[tx + 32] + red[tx + 64];
        #pragma unroll
        for (int o = 16; o > 0; o >>= 1)
            s += __shfl_down_sync(0xffffffffu, s, o);
        if (tx == 0) out[g] = s + b2[0];
    }
}

// ---------------- launch ----------------
extern "C" void kernel_launch(void* const* d_in, const int* in_sizes, int n_in,
                              void* d_out, int out_size) {
    const float* x       = (const float*)d_in[0];
    const int*   ei      = (const int*)  d_in[1];
    const int*   src     = ei;
    const int*   dst     = ei + NE;
    // d_in[2] = batch (unused, all zeros)
    const int*   central = (const int*)  d_in[3];
    const float* W_emb   = (const float*)d_in[4];
    const float* b_emb   = (const float*)d_in[5];
    const float* conv_wl = (const float*)d_in[6];
    const float* conv_bl = (const float*)d_in[7];
    const float* conv_wr = (const float*)d_in[8];
    const float* gamma   = (const float*)d_in[9];
    const float* beta    = (const float*)d_in[10];
    const float* W1      = (const float*)d_in[11];
    const float* b1      = (const float*)d_in[12];
    const float* W2      = (const float*)d_in[13];
    const float* b2      = (const float*)d_in[14];
    float* out = (float*)d_out;

    static_assert(GEMM_SMEM_FLOATS * 4 == 99584, "smem size");
    cudaFuncSetAttribute(sage_gemm_kernel,
                         cudaFuncAttributeMaxDynamicSharedMemorySize,
                         GEMM_SMEM_FLOATS * 4);

    // CSR build + BN-state init (per replay, deterministic)
    zero_deg_kernel<<<(NN + 255) / 256, 256>>>();
    count_kernel<<<(NE + 255) / 256, 256>>>(dst);
    scan_kernel<<<1, 1024>>>();
    place_kernel<<<(NE + 255) / 256, 256>>>(src, dst);

    // embedding
    embed_kernel<<<GRID_P, 128>>>(x, W_emb, b_emb);

    for (int l = 0; l < 3; l++) {
        agg_kernel<<<(NN * 32 + 255) / 256, 256>>>();
        sage_gemm_kernel<<<GRID_P, 128, GEMM_SMEM_FLOATS * 4>>>(
            conv_wl + l * HID * HID, conv_bl + l * HID, conv_wr + l * HID * HID);
        bn_finalize_kernel<<<1, HID>>>(gamma + l * HID, beta + l * HID);
    }

    final_kernel<<<512, HID>>>(central, W1, b1, W2, b2, out);
}

// round 17
// speedup vs baseline: 1.1947x; 1.1947x over previous
#include <cuda_runtime.h>
#include <cuda_bf16.h>
#include <cstdint>

#define NN 100000
#define NE 800000
#define HID 96
#define IND 64
#define BN_EPS 1e-5f
#define GRID_P 304                 // 2 CTAs x 152 SMs (GB300)

// ---- mma.sync GEMM config ----
#define GRID_MMA 304               // 2 CTAs/SM, 4 warps each -> 1216 warps
#define N_ROWTILES (NN / 16)       // 6250 (exact)
#define WARPS_TOTAL (GRID_MMA * 4) // 1216

// smem layout for sage_mma_kernel, in uint32 units
// 4 weight matrices, transposed bf16x2: [n(96)][kpair(48)] padded to stride 49
#define WLH 0
#define WLL 4704
#define WRH 9408
#define WRL 14112
#define FSCALE 18816
#define FSHIFT 18912
#define FBIAS  19008
#define FSUM   19104
#define FSQ    19200
#define SM_U32 19296               // *4 = 77184 bytes

// ---------------- persistent device scratch ----------------
__device__ float g_h2[NN * HID];     // pre-BN activations (consumers apply BN+ReLU)
__device__ float g_agg[NN * HID];    // mean-aggregated (post-BN) neighbors
__device__ int   g_deg[NN];
__device__ int   g_off[NN + 1];
__device__ int   g_cur[NN];
__device__ int   g_csr[NE];
__device__ float g_sum[HID];
__device__ float g_sq[HID];
__device__ float g_scale[HID];
__device__ float g_shift[HID];

// bf16 hi/lo split of a float2 (k-pair): hi = truncate, lo = rn(residual).
// low 16 bits of each word = even-k element (matches mma A/B fragment packing).
__device__ __forceinline__ void split2(float f0, float f1, uint32_t& hi, uint32_t& lo) {
    uint32_t b0 = __float_as_uint(f0), b1 = __float_as_uint(f1);
    hi = (b0 >> 16) | (b1 & 0xFFFF0000u);
    float h0 = __uint_as_float(b0 & 0xFFFF0000u);
    float h1 = __uint_as_float(b1 & 0xFFFF0000u);
    __nv_bfloat16 l0 = __float2bfloat16_rn(f0 - h0);
    __nv_bfloat16 l1 = __float2bfloat16_rn(f1 - h1);
    lo = (uint32_t)__bfloat16_as_ushort(l0) | ((uint32_t)__bfloat16_as_ushort(l1) << 16);
}

#define MMA4(d, A, b0_, b1_) \
    asm volatile("mma.sync.aligned.m16n8k16.row.col.f32.bf16.bf16.f32 " \
        "{%0,%1,%2,%3}, {%4,%5,%6,%7}, {%8,%9}, {%0,%1,%2,%3};" \
        : "+f"(d[0]), "+f"(d[1]), "+f"(d[2]), "+f"(d[3]) \
        : "r"(A[0]), "r"(A[1]), "r"(A[2]), "r"(A[3]), "r"(b0_), "r"(b1_))

// ---------------- CSR build + state init ----------------
__global__ void zero_deg_kernel() {
    int i = blockIdx.x * blockDim.x + threadIdx.x;
    if (i < NN) { g_deg[i] = 0; g_cur[i] = 0; }
    if (i < HID) {
        g_sum[i] = 0.f; g_sq[i] = 0.f;
        g_scale[i] = 1.f; g_shift[i] = 0.f;   // identity BN for layer-0 input
    }
}
__global__ void count_kernel(const int* __restrict__ dst) {
    int e = blockIdx.x * blockDim.x + threadIdx.x;
    if (e < NE) atomicAdd(&g_deg[dst[e]], 1);
}
__global__ void scan_kernel() {
    __shared__ int ssum[1024];
    int t = threadIdx.x;
    const int CH = (NN + 1023) / 1024;
    int start = t * CH;
    int end = start + CH; if (end > NN) end = NN;
    int local = 0;
    if (start < NN) for (int i = start; i < end; i++) local += g_deg[i];
    ssum[t] = local;
    __syncthreads();
    for (int o = 1; o < 1024; o <<= 1) {
        int v = 0;
        if (t >= o) v = ssum[t - o];
        __syncthreads();
        if (t >= o) ssum[t] += v;
        __syncthreads();
    }
    int run = ssum[t] - local;
    if (start < NN) for (int i = start; i < end; i++) { g_off[i] = run; run += g_deg[i]; }
    if (t == 1023) g_off[NN] = ssum[1023];
}
__global__ void place_kernel(const int* __restrict__ src, const int* __restrict__ dst) {
    int e = blockIdx.x * blockDim.x + threadIdx.x;
    if (e < NE) {
        int d = dst[e];
        int p = g_off[d] + atomicAdd(&g_cur[d], 1);
        g_csr[p] = src[e];
    }
}

// ---------------- embedding: h2 = relu(x @ W_emb + b_emb) ----------------
__global__ void __launch_bounds__(128) embed_kernel(const float* __restrict__ x,
                                                    const float* __restrict__ W,
                                                    const float* __restrict__ b) {
    __shared__ float sW[IND * HID];
    __shared__ float sX[32 * 65];
    int tx = threadIdx.x;
    for (int i = tx; i < IND * HID; i += 128) sW[i] = W[i];
    int rg = tx >> 4, cg = tx & 15;
    int r = rg * 4, c = cg * 6;
    for (int tile = blockIdx.x; tile < NN / 32; tile += gridDim.x) {
        __syncthreads();
        int rb = tile * 32 * IND;
        for (int i = tx; i < 32 * IND; i += 128)
            sX[(i >> 6) * 65 + (i & 63)] = x[rb + i];
        __syncthreads();
        float acc[4][6];
        #pragma unroll
        for (int i = 0; i < 4; i++)
            #pragma unroll
            for (int j = 0; j < 6; j++) acc[i][j] = 0.f;
        #pragma unroll 8
        for (int k = 0; k < IND; k++) {
            float av[4], wv[6];
            #pragma unroll
            for (int i = 0; i < 4; i++) av[i] = sX[(r + i) * 65 + k];
            #pragma unroll
            for (int j = 0; j < 6; j++) wv[j] = sW[k * HID + c + j];
            #pragma unroll
            for (int i = 0; i < 4; i++)
                #pragma unroll
                for (int j = 0; j < 6; j++)
                    acc[i][j] = fmaf(av[i], wv[j], acc[i][j]);
        }
        int ob = tile * 32 * HID;
        #pragma unroll
        for (int i = 0; i < 4; i++)
            #pragma unroll
            for (int j = 0; j < 6; j++) {
                float v = acc[i][j] + b[c + j];
                g_h2[ob + (r + i) * HID + c + j] = fmaxf(v, 0.f);
            }
    }
}

// ---------------- aggregation: warp per node; BN+ReLU on gather ----------------
__global__ void agg_kernel() {
    int w = (blockIdx.x * blockDim.x + threadIdx.x) >> 5;
    int lane = threadIdx.x & 31;
    if (w >= NN) return;
    float sc0 = g_scale[lane],      sh0 = g_shift[lane];
    float sc1 = g_scale[lane + 32], sh1 = g_shift[lane + 32];
    float sc2 = g_scale[lane + 64], sh2 = g_shift[lane + 64];
    int base = g_off[w];
    int cnt = g_deg[w];
    float a0 = 0.f, a1 = 0.f, a2 = 0.f;
    #pragma unroll 4
    for (int e = 0; e < cnt; e++) {
        int s = g_csr[base + e] * HID;
        a0 += fmaxf(fmaf(g_h2[s + lane],      sc0, sh0), 0.f);
        a1 += fmaxf(fmaf(g_h2[s + lane + 32], sc1, sh1), 0.f);
        a2 += fmaxf(fmaf(g_h2[s + lane + 64], sc2, sh2), 0.f);
    }
    float inv = 1.f / (float)(cnt > 0 ? cnt : 1);
    int o = w * HID;
    g_agg[o + lane]      = a0 * inv;
    g_agg[o + lane + 32] = a1 * inv;
    g_agg[o + lane + 64] = a2 * inv;
}

// ---------------- mma.sync SAGE GEMM: h2' = agg@Wl + bl + BN(h2)@Wr (+ BN stats) ----
// bf16 split precision via warp-level HMMA m16n8k16 (base-target, no tcgen05).
// Each warp: 16-row x 96-col output tile; weights as bf16x2 hi/lo in smem [n][kpair].
__global__ void __launch_bounds__(128) sage_mma_kernel(const float* __restrict__ Wl,
                                                       const float* __restrict__ bl,
                                                       const float* __restrict__ Wr) {
    extern __shared__ uint32_t sm[];
    float* smf = (float*)sm;
    int tid = threadIdx.x;
    int lane = tid & 31;
    int wid = tid >> 5;

    // stage transposed split weights: u16 index = (n*49 + k/2)*2 + (k&1)
    for (int i = tid; i < HID * HID; i += 128) {
        int k = i / HID, n = i - (i / HID) * HID;
        int u16i = (n * 49 + (k >> 1)) * 2 + (k & 1);
        float wl = Wl[i], wr = Wr[i];
        uint32_t bwl = __float_as_uint(wl), bwr = __float_as_uint(wr);
        ((uint16_t*)(sm + WLH))[u16i] = (uint16_t)(bwl >> 16);
        ((uint16_t*)(sm + WRH))[u16i] = (uint16_t)(bwr >> 16);
        float hl = __uint_as_float(bwl & 0xFFFF0000u);
        float hr = __uint_as_float(bwr & 0xFFFF0000u);
        ((uint16_t*)(sm + WLL))[u16i] = __bfloat16_as_ushort(__float2bfloat16_rn(wl - hl));
        ((uint16_t*)(sm + WRL))[u16i] = __bfloat16_as_ushort(__float2bfloat16_rn(wr - hr));
    }
    if (tid < HID) {
        smf[FSCALE + tid] = g_scale[tid];
        smf[FSHIFT + tid] = g_shift[tid];
        smf[FBIAS  + tid] = bl[tid];
        smf[FSUM   + tid] = 0.f;
        smf[FSQ    + tid] = 0.f;
    }
    __syncthreads();

    int r0 = lane >> 2;          // fragment row base (0..7)
    int kq = (lane & 3) * 2;     // fragment k/col base
    int gw = blockIdx.x * 4 + wid;

    float csum[24], csq[24];
    #pragma unroll
    for (int j = 0; j < 24; j++) { csum[j] = 0.f; csq[j] = 0.f; }

    for (int rt = gw; rt < N_ROWTILES; rt += WARPS_TOTAL) {
        int row = rt * 16;
        float acc[12][4];
        #pragma unroll
        for (int nt = 0; nt < 12; nt++)
            #pragma unroll
            for (int j = 0; j < 4; j++) acc[nt][j] = 0.f;

        #pragma unroll
        for (int ch = 0; ch < 6; ch++) {
            int k0 = ch * 16 + kq;
            float2 sc0 = *(const float2*)&smf[FSCALE + k0];
            float2 sh0 = *(const float2*)&smf[FSHIFT + k0];
            float2 sc8 = *(const float2*)&smf[FSCALE + k0 + 8];
            float2 sh8 = *(const float2*)&smf[FSHIFT + k0 + 8];
            float2 a0 = *(const float2*)&g_agg[(row + r0) * HID + k0];
            float2 a1 = *(const float2*)&g_agg[(row + r0 + 8) * HID + k0];
            float2 a2 = *(const float2*)&g_agg[(row + r0) * HID + k0 + 8];
            float2 a3 = *(const float2*)&g_agg[(row + r0 + 8) * HID + k0 + 8];
            float2 h0 = *(const float2*)&g_h2[(row + r0) * HID + k0];
            float2 h1 = *(const float2*)&g_h2[(row + r0 + 8) * HID + k0];
            float2 h2v = *(const float2*)&g_h2[(row + r0) * HID + k0 + 8];
            float2 h3 = *(const float2*)&g_h2[(row + r0 + 8) * HID + k0 + 8];
            h0.x = fmaxf(fmaf(h0.x, sc0.x, sh0.x), 0.f);
            h0.y = fmaxf(fmaf(h0.y, sc0.y, sh0.y), 0.f);
            h1.x = fmaxf(fmaf(h1.x, sc0.x, sh0.x), 0.f);
            h1.y = fmaxf(fmaf(h1.y, sc0.y, sh0.y), 0.f);
            h2v.x = fmaxf(fmaf(h2v.x, sc8.x, sh8.x), 0.f);
            h2v.y = fmaxf(fmaf(h2v.y, sc8.y, sh8.y), 0.f);
            h3.x = fmaxf(fmaf(h3.x, sc8.x, sh8.x), 0.f);
            h3.y = fmaxf(fmaf(h3.y, sc8.y, sh8.y), 0.f);
            uint32_t AH[4], AL[4], HH[4], HL[4];
            split2(a0.x, a0.y, AH[0], AL[0]);
            split2(a1.x, a1.y, AH[1], AL[1]);
            split2(a2.x, a2.y, AH[2], AL[2]);
            split2(a3.x, a3.y, AH[3], AL[3]);
            split2(h0.x, h0.y, HH[0], HL[0]);
            split2(h1.x, h1.y, HH[1], HL[1]);
            split2(h2v.x, h2v.y, HH[2], HL[2]);
            split2(h3.x, h3.y, HH[3], HL[3]);
            #pragma unroll
            for (int nt = 0; nt < 12; nt++) {
                int bidx = (nt * 8 + r0) * 49 + ch * 8 + (lane & 3);
                uint32_t blh0 = sm[WLH + bidx], blh1 = sm[WLH + bidx + 4];
                uint32_t bll0 = sm[WLL + bidx], bll1 = sm[WLL + bidx + 4];
                uint32_t brh0 = sm[WRH + bidx], brh1 = sm[WRH + bidx + 4];
                uint32_t brl0 = sm[WRL + bidx], brl1 = sm[WRL + bidx + 4];
                MMA4(acc[nt], AH, blh0, blh1);
                MMA4(acc[nt], AL, blh0, blh1);
                MMA4(acc[nt], AH, bll0, bll1);
                MMA4(acc[nt], HH, brh0, brh1);
                MMA4(acc[nt], HL, brh0, brh1);
                MMA4(acc[nt], HH, brl0, brl1);
            }
        }
        // epilogue: + bias, store h2 (in place; rows owned exclusively), stats
        #pragma unroll
        for (int nt = 0; nt < 12; nt++) {
            int c = nt * 8 + kq;
            float b0v = smf[FBIAS + c], b1v = smf[FBIAS + c + 1];
            float v0 = acc[nt][0] + b0v, v1 = acc[nt][1] + b1v;
            float v2 = acc[nt][2] + b0v, v3 = acc[nt][3] + b1v;
            *(float2*)&g_h2[(row + r0) * HID + c]     = make_float2(v0, v1);
            *(float2*)&g_h2[(row + r0 + 8) * HID + c] = make_float2(v2, v3);
            csum[2 * nt]     += v0 + v2;
            csum[2 * nt + 1] += v1 + v3;
            csq[2 * nt]     = fmaf(v0, v0, fmaf(v2, v2, csq[2 * nt]));
            csq[2 * nt + 1] = fmaf(v1, v1, fmaf(v3, v3, csq[2 * nt + 1]));
        }
    }
    __syncthreads();
    #pragma unroll
    for (int nt = 0; nt < 12; nt++) {
        int c = nt * 8 + kq;
        atomicAdd(&smf[FSUM + c],     csum[2 * nt]);
        atomicAdd(&smf[FSUM + c + 1], csum[2 * nt + 1]);
        atomicAdd(&smf[FSQ + c],      csq[2 * nt]);
        atomicAdd(&smf[FSQ + c + 1],  csq[2 * nt + 1]);
    }
    __syncthreads();
    if (tid < HID) {
        atomicAdd(&g_sum[tid], smf[FSUM + tid]);
        atomicAdd(&g_sq[tid],  smf[FSQ + tid]);
    }
}

// ---------------- BN finalize (+ reset accumulators) ----------------
__global__ void bn_finalize_kernel(const float* __restrict__ gamma,
                                   const float* __restrict__ beta) {
    int c = threadIdx.x;
    if (c < HID) {
        const float invN = 1.f / (float)NN;
        float mean = g_sum[c] * invN;
        float var = g_sq[c] * invN - mean * mean;
        var = fmaxf(var, 0.f);
        float sc = gamma[c] * rsqrtf(var + BN_EPS);
        g_scale[c] = sc;
        g_shift[c] = beta[c] - mean * sc;
        g_sum[c] = 0.f;
        g_sq[c]  = 0.f;
    }
}

// ---------------- final MLP on central nodes (layer-2 BN inline) ----------------
__global__ void final_kernel(const int* __restrict__ central,
                             const float* __restrict__ W1,
                             const float* __restrict__ b1,
                             const float* __restrict__ W2,
                             const float* __restrict__ b2,
                             float* __restrict__ out) {
    __shared__ float row[HID];
    __shared__ float red[HID];
    int g = blockIdx.x;
    int tx = threadIdx.x;
    int cidx = central[g];
    float raw = g_h2[cidx * HID + tx];
    row[tx] = fmaxf(fmaf(raw, g_scale[tx], g_shift[tx]), 0.f);
    __syncthreads();
    float acc = b1[tx];
    #pragma unroll 8
    for (int k = 0; k < HID; k++)
        acc = fmaf(row[k], W1[k * HID + tx], acc);
    acc = fmaxf(acc, 0.f) * W2[tx];
    red[tx] = acc;
    __syncthreads();
    if (tx < 32) {
        float s = red[tx] + red[tx + 32] + red[tx + 64];
        #pragma unroll
        for (int o = 16; o > 0; o >>= 1)
            s += __shfl_down_sync(0xffffffffu, s, o);
        if (tx == 0) out[g] = s + b2[0];
    }
}

// ---------------- launch ----------------
extern "C" void kernel_launch(void* const* d_in, const int* in_sizes, int n_in,
                              void* d_out, int out_size) {
    const float* x       = (const float*)d_in[0];
    const int*   ei      = (const int*)  d_in[1];
    const int*   src     = ei;
    const int*   dst     = ei + NE;
    const int*   central = (const int*)  d_in[3];
    const float* W_emb   = (const float*)d_in[4];
    const float* b_emb   = (const float*)d_in[5];
    const float* conv_wl = (const float*)d_in[6];
    const float* conv_bl = (const float*)d_in[7];
    const float* conv_wr = (const float*)d_in[8];
    const float* gamma   = (const float*)d_in[9];
    const float* beta    = (const float*)d_in[10];
    const float* W1      = (const float*)d_in[11];
    const float* b1      = (const float*)d_in[12];
    const float* W2      = (const float*)d_in[13];
    const float* b2      = (const float*)d_in[14];
    float* out = (float*)d_out;

    static_assert(SM_U32 * 4 == 77184, "smem layout");
    cudaFuncSetAttribute(sage_mma_kernel,
                         cudaFuncAttributeMaxDynamicSharedMemorySize, SM_U32 * 4);

    // CSR build + BN-state init
    zero_deg_kernel<<<(NN + 255) / 256, 256>>>();
    count_kernel<<<(NE + 255) / 256, 256>>>(dst);
    scan_kernel<<<1, 1024>>>();
    place_kernel<<<(NE + 255) / 256, 256>>>(src, dst);

    embed_kernel<<<GRID_P, 128>>>(x, W_emb, b_emb);

    for (int l = 0; l < 3; l++) {
        agg_kernel<<<(NN * 32 + 255) / 256, 256>>>();
        sage_mma_kernel<<<GRID_MMA, 128, SM_U32 * 4>>>(
            conv_wl + l * HID * HID, conv_bl + l * HID, conv_wr + l * HID * HID);
        bn_finalize_kernel<<<1, HID>>>(gamma + l * HID, beta + l * HID);
    }

    final_kernel<<<512, HID>>>(central, W1, b1, W2, b2, out);
}